// round 1
// baseline (speedup 1.0000x reference)
#include <cuda_runtime.h>
#include <cuda_bf16.h>
#include <cstdint>

// ---------------------------------------------------------------------------
// Problem constants
// ---------------------------------------------------------------------------
#define BATCH   4
#define SEQLEN  2048
#define DIM     1024
#define NHEADS  16
#define HDIM    64
#define MROWS   (BATCH * SEQLEN)     // 8192
#define BHCOUNT (BATCH * NHEADS)     // 64

// ---------------------------------------------------------------------------
// Scratch (static device globals -- allocation-free)
// ---------------------------------------------------------------------------
__device__ float g_q[(size_t)BHCOUNT * SEQLEN * HDIM];    // [bh][l][d]
__device__ float g_k[(size_t)BHCOUNT * SEQLEN * HDIM];
__device__ float g_v[(size_t)BHCOUNT * SEQLEN * HDIM];
__device__ float g_att[(size_t)MROWS * DIM];              // [b*L + l][h*64+d]

// ---------------------------------------------------------------------------
// SGEMM: C[m][n] = sum_k A[m][k] * B[n][k]   (A: [8192,1024], B: [1024,1024])
// mode 0: scatter epilogue to [bh][l][d] layout (QKV projections)
// mode 1: plain row-major [m][n] (attention-out projection / final output)
// ---------------------------------------------------------------------------
#define GBM 128
#define GBN 128
#define GBK 16
#define GLDA 132   // 128 + 4 pad; 132*4 bytes divisible by 16 -> float4-aligned rows

__global__ __launch_bounds__(256, 2)
void sgemm_nt_kernel(const float* __restrict__ A, const float* __restrict__ B,
                     float* __restrict__ C, int mode)
{
    __shared__ float As[GBK][GLDA];
    __shared__ float Bs[GBK][GLDA];

    const int K = DIM;
    const int tid = threadIdx.x;
    const int tx  = tid & 15;
    const int ty  = tid >> 4;
    const int row0 = blockIdx.y * GBM;
    const int col0 = blockIdx.x * GBN;

    const int ldr = tid >> 2;          // 0..63
    const int ldc = (tid & 3) << 2;    // 0,4,8,12

    const float* Aptr = A + (size_t)(row0 + ldr) * K + ldc;
    const float* Bptr = B + (size_t)(col0 + ldr) * K + ldc;

    float acc[8][8];
#pragma unroll
    for (int i = 0; i < 8; i++)
#pragma unroll
        for (int j = 0; j < 8; j++) acc[i][j] = 0.0f;

    for (int k0 = 0; k0 < K; k0 += GBK) {
#pragma unroll
        for (int h = 0; h < 2; h++) {
            float4 av = *(const float4*)(Aptr + (size_t)h * 64 * K + k0);
            As[ldc + 0][ldr + h * 64] = av.x;
            As[ldc + 1][ldr + h * 64] = av.y;
            As[ldc + 2][ldr + h * 64] = av.z;
            As[ldc + 3][ldr + h * 64] = av.w;
            float4 bv = *(const float4*)(Bptr + (size_t)h * 64 * K + k0);
            Bs[ldc + 0][ldr + h * 64] = bv.x;
            Bs[ldc + 1][ldr + h * 64] = bv.y;
            Bs[ldc + 2][ldr + h * 64] = bv.z;
            Bs[ldc + 3][ldr + h * 64] = bv.w;
        }
        __syncthreads();

#pragma unroll
        for (int k = 0; k < GBK; k++) {
            float4 a0 = *(const float4*)(&As[k][ty * 8]);
            float4 a1 = *(const float4*)(&As[k][ty * 8 + 4]);
            float4 b0 = *(const float4*)(&Bs[k][tx * 8]);
            float4 b1 = *(const float4*)(&Bs[k][tx * 8 + 4]);
            float ar[8] = {a0.x, a0.y, a0.z, a0.w, a1.x, a1.y, a1.z, a1.w};
            float br[8] = {b0.x, b0.y, b0.z, b0.w, b1.x, b1.y, b1.z, b1.w};
#pragma unroll
            for (int i = 0; i < 8; i++)
#pragma unroll
                for (int j = 0; j < 8; j++)
                    acc[i][j] = fmaf(ar[i], br[j], acc[i][j]);
        }
        __syncthreads();
    }

    if (mode == 0) {
        // scatter to [bh][l][d]: bh = b*16 + (n/64), d = n%64
#pragma unroll
        for (int i = 0; i < 8; i++) {
            int m = row0 + ty * 8 + i;
            int b = m >> 11, l = m & 2047;
#pragma unroll
            for (int j = 0; j < 8; j++) {
                int n = col0 + tx * 8 + j;
                int h = n >> 6, d = n & 63;
                C[((size_t)(b * NHEADS + h) * SEQLEN + l) * HDIM + d] = acc[i][j];
            }
        }
    } else {
#pragma unroll
        for (int i = 0; i < 8; i++) {
            int m = row0 + ty * 8 + i;
            float* cp = C + (size_t)m * DIM + col0 + tx * 8;
#pragma unroll
            for (int j = 0; j < 8; j++) cp[j] = acc[i][j];
        }
    }
}

// ---------------------------------------------------------------------------
// Flash attention with diagonal (self) masking.
// One block = (bh, 64-query tile). 256 threads as 16x16, each owns a 4x4
// micro-tile of S and of O. Online softmax in exp2 domain.
// Smem: Qst (d-major), KPs (K d-major, reused as P j-major), Vs (row-major).
// ---------------------------------------------------------------------------
#define ATP 68                                  // padded row stride (floats); 68*4 % 16 == 0
#define ATT_SMEM (3 * 64 * ATP * (int)sizeof(float))   // 52224 bytes

__global__ __launch_bounds__(256, 2)
void attn_kernel()
{
    extern __shared__ float sm[];
    float* Qst = sm;                 // [64 d][ATP] : Qst[d*ATP + i]
    float* KPs = sm + 64 * ATP;      // K: [64 d][ATP] -> reused as P: [64 j][ATP]
    float* Vs  = sm + 2 * 64 * ATP;  // [64 j][ATP]  : Vs[j*ATP + c]

    const int bh = blockIdx.y;
    const int b  = bh >> 4;
    const int h  = bh & 15;
    const float* Q  = g_q + (size_t)bh * SEQLEN * HDIM;
    const float* Kg = g_k + (size_t)bh * SEQLEN * HDIM;
    const float* Vg = g_v + (size_t)bh * SEQLEN * HDIM;
    const int q0  = blockIdx.x * 64;
    const int tid = threadIdx.x;
    const int tx  = tid & 15;
    const int ty  = tid >> 4;
    const int r0  = ty * 4;
    const int c0  = tx * 4;

    // load Q tile (transpose to d-major)
#pragma unroll
    for (int it = 0; it < 4; it++) {
        int idx = tid + it * 256;
        int row = idx >> 4;
        int cc  = (idx & 15) << 2;
        float4 v = *(const float4*)(Q + (size_t)(q0 + row) * HDIM + cc);
        Qst[(cc + 0) * ATP + row] = v.x;
        Qst[(cc + 1) * ATP + row] = v.y;
        Qst[(cc + 2) * ATP + row] = v.z;
        Qst[(cc + 3) * ATP + row] = v.w;
    }

    float accO[4][4];
#pragma unroll
    for (int i = 0; i < 4; i++)
#pragma unroll
        for (int c = 0; c < 4; c++) accO[i][c] = 0.0f;

    float mreg[4], lreg[4];
#pragma unroll
    for (int i = 0; i < 4; i++) { mreg[i] = -1e30f; lreg[i] = 0.0f; }

    const float sc = 0.125f * 1.44269504088896340736f;   // 1/sqrt(64) * log2(e)

    for (int n0 = 0; n0 < SEQLEN; n0 += 64) {
        // load K (transposed, d-major) and V (row-major)
#pragma unroll
        for (int it = 0; it < 4; it++) {
            int idx = tid + it * 256;
            int row = idx >> 4;
            int cc  = (idx & 15) << 2;
            float4 kv = *(const float4*)(Kg + (size_t)(n0 + row) * HDIM + cc);
            KPs[(cc + 0) * ATP + row] = kv.x;
            KPs[(cc + 1) * ATP + row] = kv.y;
            KPs[(cc + 2) * ATP + row] = kv.z;
            KPs[(cc + 3) * ATP + row] = kv.w;
            float4 vv = *(const float4*)(Vg + (size_t)(n0 + row) * HDIM + cc);
            *(float4*)(Vs + row * ATP + cc) = vv;
        }
        __syncthreads();

        // S = Q K^T (4x4 micro-tile per thread)
        float accS[4][4];
#pragma unroll
        for (int i = 0; i < 4; i++)
#pragma unroll
            for (int j = 0; j < 4; j++) accS[i][j] = 0.0f;

#pragma unroll 8
        for (int d = 0; d < HDIM; d++) {
            float4 a  = *(const float4*)(Qst + d * ATP + r0);
            float4 bb = *(const float4*)(KPs + d * ATP + c0);
            float ar[4] = {a.x, a.y, a.z, a.w};
            float br[4] = {bb.x, bb.y, bb.z, bb.w};
#pragma unroll
            for (int i = 0; i < 4; i++)
#pragma unroll
                for (int j = 0; j < 4; j++)
                    accS[i][j] = fmaf(ar[i], br[j], accS[i][j]);
        }

        // scale (exp2 domain), diagonal mask, local row max
        float tmax[4];
#pragma unroll
        for (int i = 0; i < 4; i++) {
            tmax[i] = -1e30f;
#pragma unroll
            for (int j = 0; j < 4; j++) {
                float t = accS[i][j] * sc;
                if (q0 + r0 + i == n0 + c0 + j) t = -1e30f;
                accS[i][j] = t;
                tmax[i] = fmaxf(tmax[i], t);
            }
        }
        // reduce max across the 16 threads sharing these rows (16-lane halves)
#pragma unroll
        for (int off = 8; off; off >>= 1)
#pragma unroll
            for (int i = 0; i < 4; i++)
                tmax[i] = fmaxf(tmax[i], __shfl_xor_sync(0xffffffffu, tmax[i], off));

        float alpha[4], tsum[4];
#pragma unroll
        for (int i = 0; i < 4; i++) {
            float mnew = fmaxf(mreg[i], tmax[i]);
            alpha[i] = exp2f(mreg[i] - mnew);
            mreg[i] = mnew;
            tsum[i] = 0.0f;
#pragma unroll
            for (int j = 0; j < 4; j++) {
                float p = exp2f(accS[i][j] - mnew);
                accS[i][j] = p;
                tsum[i] += p;
            }
        }
#pragma unroll
        for (int off = 8; off; off >>= 1)
#pragma unroll
            for (int i = 0; i < 4; i++)
                tsum[i] += __shfl_xor_sync(0xffffffffu, tsum[i], off);
#pragma unroll
        for (int i = 0; i < 4; i++)
            lreg[i] = lreg[i] * alpha[i] + tsum[i];

#pragma unroll
        for (int i = 0; i < 4; i++)
#pragma unroll
            for (int c = 0; c < 4; c++) accO[i][c] *= alpha[i];

        // write P into smem (reusing K buffer), j-major
        __syncthreads();   // everyone finished reading Kst
#pragma unroll
        for (int i = 0; i < 4; i++)
#pragma unroll
            for (int j = 0; j < 4; j++)
                KPs[(c0 + j) * ATP + (r0 + i)] = accS[i][j];
        __syncthreads();

        // O += P V
#pragma unroll 8
        for (int j = 0; j < 64; j++) {
            float4 a  = *(const float4*)(KPs + j * ATP + r0);
            float4 vv = *(const float4*)(Vs + j * ATP + c0);
            float ar[4] = {a.x, a.y, a.z, a.w};
            float vr[4] = {vv.x, vv.y, vv.z, vv.w};
#pragma unroll
            for (int i = 0; i < 4; i++)
#pragma unroll
                for (int c = 0; c < 4; c++)
                    accO[i][c] = fmaf(ar[i], vr[c], accO[i][c]);
        }
        __syncthreads();   // before next tile overwrites KPs / Vs
    }

    // epilogue: normalize and write to [b][l][h*64+d]
#pragma unroll
    for (int i = 0; i < 4; i++) {
        float inv = 1.0f / lreg[i];
        int l = q0 + r0 + i;
        float* op = g_att + ((size_t)(b * SEQLEN + l)) * DIM + h * HDIM + c0;
#pragma unroll
        for (int c = 0; c < 4; c++) op[c] = accO[i][c] * inv;
    }
}

// ---------------------------------------------------------------------------
// Launch
// ---------------------------------------------------------------------------
extern "C" void kernel_launch(void* const* d_in, const int* in_sizes, int n_in,
                              void* d_out, int out_size)
{
    const float* x  = (const float*)d_in[0];
    const float* wq = (const float*)d_in[1];
    const float* wk = (const float*)d_in[2];
    const float* wv = (const float*)d_in[3];
    const float* wo = (const float*)d_in[4];
    float* out = (float*)d_out;

    float *pq, *pk, *pv, *patt;
    cudaGetSymbolAddress((void**)&pq,  g_q);
    cudaGetSymbolAddress((void**)&pk,  g_k);
    cudaGetSymbolAddress((void**)&pv,  g_v);
    cudaGetSymbolAddress((void**)&patt, g_att);

    dim3 ggrid(DIM / GBN, MROWS / GBM);   // (8, 64)

    sgemm_nt_kernel<<<ggrid, 256>>>(x, wq, pq, 0);
    sgemm_nt_kernel<<<ggrid, 256>>>(x, wk, pk, 0);
    sgemm_nt_kernel<<<ggrid, 256>>>(x, wv, pv, 0);

    cudaFuncSetAttribute(attn_kernel,
                         cudaFuncAttributeMaxDynamicSharedMemorySize, ATT_SMEM);
    attn_kernel<<<dim3(SEQLEN / 64, BHCOUNT), 256, ATT_SMEM>>>();

    sgemm_nt_kernel<<<ggrid, 256>>>(patt, wo, out, 1);
}

// round 14
// speedup vs baseline: 2.5993x; 2.5993x over previous
#include <cuda_runtime.h>
#include <cuda_fp16.h>
#include <cstdint>

// ---------------------------------------------------------------------------
// Problem constants
// ---------------------------------------------------------------------------
#define BATCH   4
#define SEQLEN  2048
#define DIM     1024
#define NHEADS  16
#define HDIM    64
#define MROWS   (BATCH * SEQLEN)     // 8192
#define BHCOUNT (BATCH * NHEADS)     // 64

// ---------------------------------------------------------------------------
// Scratch (static device globals -- allocation-free)
// ---------------------------------------------------------------------------
__device__ __half g_qh[(size_t)BHCOUNT * SEQLEN * HDIM];   // Q hi  [bh][l][d]
__device__ __half g_ql[(size_t)BHCOUNT * SEQLEN * HDIM];   // Q lo
__device__ __half g_kh[(size_t)BHCOUNT * SEQLEN * HDIM];
__device__ __half g_kl[(size_t)BHCOUNT * SEQLEN * HDIM];
__device__ __half g_vh[(size_t)BHCOUNT * SEQLEN * HDIM];
__device__ __half g_vl[(size_t)BHCOUNT * SEQLEN * HDIM];
__device__ __half g_xh[(size_t)MROWS * DIM];               // x split hi
__device__ __half g_xl[(size_t)MROWS * DIM];               // x split lo
__device__ __half g_wh[(size_t)4 * DIM * DIM];             // wq,wk,wv,wo hi
__device__ __half g_wl[(size_t)4 * DIM * DIM];             // wq,wk,wv,wo lo
__device__ __half g_ath[(size_t)MROWS * DIM];              // attn out hi
__device__ __half g_atl[(size_t)MROWS * DIM];              // attn out lo

// ---------------------------------------------------------------------------
// PTX helpers (base sm_103 target: mma.sync / ldmatrix / cp.async only)
// ---------------------------------------------------------------------------
__device__ __forceinline__ uint32_t smem_to_u32(const void* p) {
    uint32_t a;
    asm("{ .reg .u64 t; cvta.to.shared.u64 t, %1; cvt.u32.u64 %0, t; }"
        : "=r"(a) : "l"(p));
    return a;
}
__device__ __forceinline__ uint32_t pack_half2(__half a, __half b) {
    __half2 h = __halves2half2(a, b);
    return *reinterpret_cast<uint32_t*>(&h);
}

#define CP_ASYNC16(smem, gptr) \
    asm volatile("cp.async.cg.shared.global [%0], [%1], 16;" \
        :: "r"(smem), "l"(gptr) : "memory")
#define CP_COMMIT() asm volatile("cp.async.commit_group;" ::: "memory")
#define CP_WAIT1()  asm volatile("cp.async.wait_group 1;" ::: "memory")
#define CP_WAIT0()  asm volatile("cp.async.wait_group 0;" ::: "memory")

#define LDSM4(r, addr) \
    asm volatile("ldmatrix.sync.aligned.m8n8.x4.shared.b16 {%0,%1,%2,%3}, [%4];" \
        : "=r"((r)[0]), "=r"((r)[1]), "=r"((r)[2]), "=r"((r)[3]) : "r"(addr))

#define LDSM4T(r, addr) \
    asm volatile("ldmatrix.sync.aligned.m8n8.x4.trans.shared.b16 {%0,%1,%2,%3}, [%4];" \
        : "=r"((r)[0]), "=r"((r)[1]), "=r"((r)[2]), "=r"((r)[3]) : "r"(addr))

#define MMA16816(d, a, b) \
    asm volatile("mma.sync.aligned.m16n8k16.row.col.f32.f16.f16.f32 " \
        "{%0,%1,%2,%3}, {%4,%5,%6,%7}, {%8,%9}, {%0,%1,%2,%3};" \
        : "+f"((d)[0]), "+f"((d)[1]), "+f"((d)[2]), "+f"((d)[3]) \
        : "r"((a)[0]), "r"((a)[1]), "r"((a)[2]), "r"((a)[3]), \
          "r"((b)[0]), "r"((b)[1]))

// fast exp2 on the FMA pipe (no MUFU). Valid for x <= 0; clamps below -126.
// Degree-6 Taylor of 2^f on [0,1): rel err ~1.5e-5.
__device__ __forceinline__ float fast_exp2(float x) {
    x = fmaxf(x, -126.0f);
    float xi = floorf(x);
    float xf = x - xi;
    float p =        1.5404563e-4f;
    p = fmaf(p, xf,  1.3333558e-3f);
    p = fmaf(p, xf,  9.6181291e-3f);
    p = fmaf(p, xf,  5.5504109e-2f);
    p = fmaf(p, xf,  2.4022651e-1f);
    p = fmaf(p, xf,  6.9314718e-1f);
    p = fmaf(p, xf,  1.0f);
    float s = __int_as_float(((int)xi + 127) << 23);
    return p * s;
}

// split one fp32 pair into packed fp16 hi and lo half2 regs
__device__ __forceinline__ void split2(float x, float y, uint32_t& hi, uint32_t& lo) {
    __half hx = __float2half_rn(x), hy = __float2half_rn(y);
    __half lx = __float2half_rn(x - __half2float(hx));
    __half ly = __float2half_rn(y - __half2float(hy));
    hi = pack_half2(hx, hy);
    lo = pack_half2(lx, ly);
}

// ---------------------------------------------------------------------------
// fp32 -> (fp16 hi, fp16 lo) split, vectorized by 4
// ---------------------------------------------------------------------------
__global__ void split_fp16_kernel(const float4* __restrict__ in,
                                  uint2* __restrict__ hi, uint2* __restrict__ lo,
                                  int n4)
{
    int i = blockIdx.x * 256 + threadIdx.x;
    if (i >= n4) return;
    float4 v = in[i];
    __half hx = __float2half_rn(v.x), hy = __float2half_rn(v.y);
    __half hz = __float2half_rn(v.z), hw = __float2half_rn(v.w);
    __half lx = __float2half_rn(v.x - __half2float(hx));
    __half ly = __float2half_rn(v.y - __half2float(hy));
    __half lz = __float2half_rn(v.z - __half2float(hz));
    __half lw = __float2half_rn(v.w - __half2float(hw));
    uint2 H, L;
    H.x = pack_half2(hx, hy); H.y = pack_half2(hz, hw);
    L.x = pack_half2(lx, ly); L.y = pack_half2(lz, lw);
    hi[i] = H;
    lo[i] = L;
}

// ---------------------------------------------------------------------------
// Split-fp16 tensor-core GEMM:  C[m][n] = sum_k A[m][k] * B[n][k]
//   D = Ah*Bh + Ah*Bl + Al*Bh   (fp32 accumulate)
// mode 0: scatter fp16 hi/lo into [bh][l][d] (QKV projections)
// mode 1: plain row-major fp32 [m][n] (final output)
// ---------------------------------------------------------------------------
#define BM 128
#define BN 128
#define BK 32
#define LDT 40                      // halves per smem row (64B data + 16B pad)
#define TILE_B (BM * LDT * 2)       // bytes per operand array: 10240
#define STAGE_B (4 * TILE_B)        // Ah, Al, Bh, Bl : 40960 bytes
#define GEMM_SMEM (2 * STAGE_B)     // double buffered: 81920 bytes
#define NT (DIM / BK)               // 32 k-tiles

__device__ __forceinline__ void gemm_load_stage(
    uint32_t sdst,
    const __half* __restrict__ Ah, const __half* __restrict__ Al,
    const __half* __restrict__ Bh, const __half* __restrict__ Bl,
    int row0, int col0, int k0, int tid)
{
#pragma unroll
    for (int p = 0; p < 2; p++) {
        int c   = tid + p * 256;         // 0..511 chunk id
        int row = c >> 2;                // 0..127
        int cc  = c & 3;                 // 16B chunk within 64B row
        uint32_t soff = (uint32_t)(row * LDT + cc * 8) * 2;
        size_t ga = (size_t)(row0 + row) * DIM + k0 + cc * 8;
        size_t gb = (size_t)(col0 + row) * DIM + k0 + cc * 8;
        CP_ASYNC16(sdst + 0 * TILE_B + soff, Ah + ga);
        CP_ASYNC16(sdst + 1 * TILE_B + soff, Al + ga);
        CP_ASYNC16(sdst + 2 * TILE_B + soff, Bh + gb);
        CP_ASYNC16(sdst + 3 * TILE_B + soff, Bl + gb);
    }
}

__global__ __launch_bounds__(256, 1)
void gemm_fp16split_kernel(const __half* __restrict__ Ah, const __half* __restrict__ Al,
                           const __half* __restrict__ Bh, const __half* __restrict__ Bl,
                           __half* __restrict__ Chi, __half* __restrict__ Clo,
                           float* __restrict__ Cf, int mode)
{
    extern __shared__ char sh[];
    const uint32_t sbase = smem_to_u32(sh);
    const int tid   = threadIdx.x;
    const int lane  = tid & 31;
    const int wid   = tid >> 5;
    const int warpM = wid & 1;          // 2 warps over M
    const int warpN = wid >> 1;         // 4 warps over N
    const int row0  = blockIdx.y * BM;
    const int col0  = blockIdx.x * BN;

    float acc[4][4][4];
#pragma unroll
    for (int i = 0; i < 4; i++)
#pragma unroll
        for (int j = 0; j < 4; j++)
#pragma unroll
            for (int r = 0; r < 4; r++) acc[i][j][r] = 0.0f;

    const int lr = lane & 15;           // ldmatrix row
    const int lc = lane >> 4;           // ldmatrix 16B-chunk

    gemm_load_stage(sbase, Ah, Al, Bh, Bl, row0, col0, 0, tid);
    CP_COMMIT();

    for (int t = 0; t < NT; t++) {
        if (t + 1 < NT) {
            gemm_load_stage(sbase + ((t + 1) & 1) * STAGE_B,
                            Ah, Al, Bh, Bl, row0, col0, (t + 1) * BK, tid);
            CP_COMMIT();
            CP_WAIT1();
        } else {
            CP_WAIT0();
        }
        __syncthreads();

        const uint32_t s0 = sbase + (t & 1) * STAGE_B;
#pragma unroll
        for (int ks = 0; ks < 2; ks++) {
            uint32_t ah[4][4], al[4][4];
#pragma unroll
            for (int mi = 0; mi < 4; mi++) {
                uint32_t off = (uint32_t)((warpM * 64 + mi * 16 + lr) * LDT
                                          + ks * 16 + lc * 8) * 2;
                LDSM4(ah[mi], s0 + 0 * TILE_B + off);
                LDSM4(al[mi], s0 + 1 * TILE_B + off);
            }
            uint32_t bh[4][2], bl[4][2];
#pragma unroll
            for (int bi = 0; bi < 2; bi++) {
                uint32_t off = (uint32_t)((warpN * 32 + bi * 16 + lr) * LDT
                                          + ks * 16 + lc * 8) * 2;
                uint32_t r[4];
                LDSM4(r, s0 + 2 * TILE_B + off);
                bh[bi * 2 + 0][0] = r[0]; bh[bi * 2 + 0][1] = r[2];
                bh[bi * 2 + 1][0] = r[1]; bh[bi * 2 + 1][1] = r[3];
                LDSM4(r, s0 + 3 * TILE_B + off);
                bl[bi * 2 + 0][0] = r[0]; bl[bi * 2 + 0][1] = r[2];
                bl[bi * 2 + 1][0] = r[1]; bl[bi * 2 + 1][1] = r[3];
            }
#pragma unroll
            for (int mi = 0; mi < 4; mi++)
#pragma unroll
                for (int ni = 0; ni < 4; ni++) {
                    MMA16816(acc[mi][ni], ah[mi], bh[ni]);
                    MMA16816(acc[mi][ni], ah[mi], bl[ni]);
                    MMA16816(acc[mi][ni], al[mi], bh[ni]);
                }
        }
        __syncthreads();
    }

    // epilogue: d-frag lane layout: rows lane>>2, lane>>2+8; cols 2*(lane&3)+{0,1}
#pragma unroll
    for (int mi = 0; mi < 4; mi++) {
        int r0g = row0 + warpM * 64 + mi * 16 + (lane >> 2);
#pragma unroll
        for (int ni = 0; ni < 4; ni++) {
            int n = col0 + warpN * 32 + ni * 8 + 2 * (lane & 3);
            if (mode == 0) {
                int h = n >> 6, d = n & 63;
#pragma unroll
                for (int hh = 0; hh < 2; hh++) {
                    int m = r0g + hh * 8;
                    int b = m >> 11, l = m & 2047;
                    uint32_t H, L;
                    split2(acc[mi][ni][hh * 2], acc[mi][ni][hh * 2 + 1], H, L);
                    size_t off = ((size_t)(b * NHEADS + h) * SEQLEN + l) * HDIM + d;
                    *(uint32_t*)(Chi + off) = H;
                    *(uint32_t*)(Clo + off) = L;
                }
            } else {
#pragma unroll
                for (int hh = 0; hh < 2; hh++) {
                    int m = r0g + hh * 8;
                    float2 v = make_float2(acc[mi][ni][hh * 2], acc[mi][ni][hh * 2 + 1]);
                    *(float2*)(Cf + (size_t)m * DIM + n) = v;
                }
            }
        }
    }
}

// ---------------------------------------------------------------------------
// HMMA flash attention with diagonal (self) masking.
//   Block: 128 queries x one (bh). 8 warps, each owns m=16 rows.
//   Per 64-key tile: S = QK^T (3-way hi/lo HMMA), softmax via fast_exp2
//   (FMA pipe, no MUFU), O += P V (3-way hi/lo HMMA, P repacked in regs).
//   K/V cp.async double-buffered. Epilogue writes fp16 hi/lo attn output.
// ---------------------------------------------------------------------------
#define AQT  128
#define AKT  64
#define APAD 72                               // halves per smem row (144B)
#define SMQ  (AQT * APAD * 2)                 // 18432 B per Q array
#define SMKV (AKT * APAD * 2)                 // 9216 B per K/V array
#define KVSTAGE (4 * SMKV)                    // Kh,Kl,Vh,Vl: 36864 B
#define ATT_SMEM (2 * SMQ + 2 * KVSTAGE)      // 110592 B

__device__ __forceinline__ void attn_load_kv(
    uint32_t kvbase,
    const __half* __restrict__ gKh, const __half* __restrict__ gKl,
    const __half* __restrict__ gVh, const __half* __restrict__ gVl,
    int n0, int tid)
{
#pragma unroll
    for (int it = 0; it < 8; it++) {
        int arr = it >> 1;                       // 0:Kh 1:Kl 2:Vh 3:Vl
        int row = (it & 1) * 32 + (tid >> 3);    // 0..63
        int cc  = tid & 7;
        const __half* src = (arr == 0 ? gKh : arr == 1 ? gKl : arr == 2 ? gVh : gVl)
                          + (size_t)(n0 + row) * HDIM + cc * 8;
        CP_ASYNC16(kvbase + arr * SMKV + (uint32_t)(row * APAD + cc * 8) * 2, src);
    }
}

__global__ __launch_bounds__(256, 2)
void attn_hmma_kernel()
{
    extern __shared__ char sm[];
    const uint32_t sb  = smem_to_u32(sm);
    const int tid  = threadIdx.x;
    const int lane = tid & 31;
    const int wid  = tid >> 5;
    const int bh   = blockIdx.y;
    const int b    = bh >> 4;
    const int h    = bh & 15;
    const int q0   = blockIdx.x * AQT;
    const int m0   = wid * 16;
    const int lmr  = lane & 15;     // ldmatrix row lane
    const int lmc  = lane >> 4;     // ldmatrix col-chunk lane

    const size_t bhoff = (size_t)bh * SEQLEN * HDIM;
    const __half* gQh = g_qh + bhoff + (size_t)q0 * HDIM;
    const __half* gQl = g_ql + bhoff + (size_t)q0 * HDIM;
    const __half* gKh = g_kh + bhoff;
    const __half* gKl = g_kl + bhoff;
    const __half* gVh = g_vh + bhoff;
    const __half* gVl = g_vl + bhoff;

    const uint32_t sQh = sb;
    const uint32_t sQl = sb + SMQ;
    const uint32_t sKV0 = sb + 2 * SMQ;

    // prologue: Q (both arrays) + KV tile 0, one commit group
#pragma unroll
    for (int it = 0; it < 8; it++) {
        int arr = it >> 2;                        // 0:Qh 1:Ql
        int row = (it & 3) * 32 + (tid >> 3);     // 0..127
        int cc  = tid & 7;
        const __half* src = (arr ? gQl : gQh) + (size_t)row * HDIM + cc * 8;
        CP_ASYNC16((arr ? sQl : sQh) + (uint32_t)(row * APAD + cc * 8) * 2, src);
    }
    attn_load_kv(sKV0, gKh, gKl, gVh, gVl, 0, tid);
    CP_COMMIT();

    float oacc[8][4];
#pragma unroll
    for (int i = 0; i < 8; i++)
#pragma unroll
        for (int e = 0; e < 4; e++) oacc[i][e] = 0.0f;
    float mrow[2] = {-1e30f, -1e30f};
    float lrow[2] = {0.0f, 0.0f};

    const float SCC = 0.125f * 1.44269504088896340736f;  // 1/sqrt(64) * log2(e)
    const int rowA = q0 + m0 + (lane >> 2);               // first row this lane owns

    for (int t = 0; t < SEQLEN / AKT; t++) {
        if (t + 1 < SEQLEN / AKT) {
            attn_load_kv(sKV0 + ((t + 1) & 1) * KVSTAGE,
                         gKh, gKl, gVh, gVl, (t + 1) * AKT, tid);
            CP_COMMIT();
            CP_WAIT1();
        } else {
            CP_WAIT0();
        }
        __syncthreads();

        const uint32_t kb = sKV0 + (t & 1) * KVSTAGE;

        // ---- S = Q K^T ----
        float sacc[8][4];
#pragma unroll
        for (int i = 0; i < 8; i++)
#pragma unroll
            for (int e = 0; e < 4; e++) sacc[i][e] = 0.0f;

#pragma unroll
        for (int ks = 0; ks < 4; ks++) {
            uint32_t ah[4], al[4];
            uint32_t qoff = (uint32_t)((m0 + lmr) * APAD + ks * 16 + lmc * 8) * 2;
            LDSM4(ah, sQh + qoff);
            LDSM4(al, sQl + qoff);
#pragma unroll
            for (int bp = 0; bp < 4; bp++) {
                uint32_t koff = (uint32_t)((bp * 16 + lmr) * APAD + ks * 16 + lmc * 8) * 2;
                uint32_t rh[4], rl[4];
                LDSM4(rh, kb + 0 * SMKV + koff);
                LDSM4(rl, kb + 1 * SMKV + koff);
                uint32_t bfh[2], bfl[2];
                bfh[0] = rh[0]; bfh[1] = rh[2];
                bfl[0] = rl[0]; bfl[1] = rl[2];
                MMA16816(sacc[2 * bp], ah, bfh);
                MMA16816(sacc[2 * bp], ah, bfl);
                MMA16816(sacc[2 * bp], al, bfh);
                bfh[0] = rh[1]; bfh[1] = rh[3];
                bfl[0] = rl[1]; bfl[1] = rl[3];
                MMA16816(sacc[2 * bp + 1], ah, bfh);
                MMA16816(sacc[2 * bp + 1], ah, bfl);
                MMA16816(sacc[2 * bp + 1], al, bfh);
            }
        }

        // ---- scale, diagonal mask, online softmax ----
        const int n0 = t * AKT;
        float tm[2] = {-1e30f, -1e30f};
#pragma unroll
        for (int nb = 0; nb < 8; nb++)
#pragma unroll
            for (int e = 0; e < 4; e++) {
                int colg = n0 + nb * 8 + 2 * (lane & 3) + (e & 1);
                int rowg = rowA + (e >> 1) * 8;
                float v = sacc[nb][e] * SCC;
                v = (rowg == colg) ? -1e30f : v;
                sacc[nb][e] = v;
                tm[e >> 1] = fmaxf(tm[e >> 1], v);
            }
        tm[0] = fmaxf(tm[0], __shfl_xor_sync(0xffffffffu, tm[0], 1));
        tm[0] = fmaxf(tm[0], __shfl_xor_sync(0xffffffffu, tm[0], 2));
        tm[1] = fmaxf(tm[1], __shfl_xor_sync(0xffffffffu, tm[1], 1));
        tm[1] = fmaxf(tm[1], __shfl_xor_sync(0xffffffffu, tm[1], 2));

        float mn0 = fmaxf(mrow[0], tm[0]);
        float mn1 = fmaxf(mrow[1], tm[1]);
        float a0 = fast_exp2(mrow[0] - mn0);
        float a1 = fast_exp2(mrow[1] - mn1);
        mrow[0] = mn0; mrow[1] = mn1;

        float rs[2] = {0.0f, 0.0f};
#pragma unroll
        for (int nb = 0; nb < 8; nb++)
#pragma unroll
            for (int e = 0; e < 4; e++) {
                float p = fast_exp2(sacc[nb][e] - ((e < 2) ? mn0 : mn1));
                sacc[nb][e] = p;
                rs[e >> 1] += p;
            }
        rs[0] += __shfl_xor_sync(0xffffffffu, rs[0], 1);
        rs[0] += __shfl_xor_sync(0xffffffffu, rs[0], 2);
        rs[1] += __shfl_xor_sync(0xffffffffu, rs[1], 1);
        rs[1] += __shfl_xor_sync(0xffffffffu, rs[1], 2);
        lrow[0] = lrow[0] * a0 + rs[0];
        lrow[1] = lrow[1] * a1 + rs[1];

#pragma unroll
        for (int nb = 0; nb < 8; nb++) {
            oacc[nb][0] *= a0; oacc[nb][1] *= a0;
            oacc[nb][2] *= a1; oacc[nb][3] *= a1;
        }

        // ---- O += P V ----
#pragma unroll
        for (int kv = 0; kv < 4; kv++) {
            uint32_t pah[4], pal[4];
            split2(sacc[2 * kv][0],     sacc[2 * kv][1],     pah[0], pal[0]);
            split2(sacc[2 * kv][2],     sacc[2 * kv][3],     pah[1], pal[1]);
            split2(sacc[2 * kv + 1][0], sacc[2 * kv + 1][1], pah[2], pal[2]);
            split2(sacc[2 * kv + 1][2], sacc[2 * kv + 1][3], pah[3], pal[3]);
#pragma unroll
            for (int db = 0; db < 4; db++) {
                uint32_t voff = (uint32_t)((kv * 16 + ((lane >> 3) & 1) * 8 + (lane & 7)) * APAD
                                           + db * 16 + (lane >> 4) * 8) * 2;
                uint32_t rvh[4], rvl[4];
                LDSM4T(rvh, kb + 2 * SMKV + voff);
                LDSM4T(rvl, kb + 3 * SMKV + voff);
                uint32_t bfh[2], bfl[2];
                bfh[0] = rvh[0]; bfh[1] = rvh[1];
                bfl[0] = rvl[0]; bfl[1] = rvl[1];
                MMA16816(oacc[2 * db], pah, bfh);
                MMA16816(oacc[2 * db], pal, bfh);
                MMA16816(oacc[2 * db], pah, bfl);
                bfh[0] = rvh[2]; bfh[1] = rvh[3];
                bfl[0] = rvl[2]; bfl[1] = rvl[3];
                MMA16816(oacc[2 * db + 1], pah, bfh);
                MMA16816(oacc[2 * db + 1], pal, bfh);
                MMA16816(oacc[2 * db + 1], pah, bfl);
            }
        }
        __syncthreads();
    }

    // ---- epilogue: normalize, split to fp16 hi/lo, write [b][l][h*64+d] ----
    float inv0 = 1.0f / lrow[0];
    float inv1 = 1.0f / lrow[1];
#pragma unroll
    for (int nb = 0; nb < 8; nb++) {
        int d = h * HDIM + nb * 8 + 2 * (lane & 3);
        uint32_t H, L;
        split2(oacc[nb][0] * inv0, oacc[nb][1] * inv0, H, L);
        size_t off0 = ((size_t)(b * SEQLEN + rowA)) * DIM + d;
        *(uint32_t*)(g_ath + off0) = H;
        *(uint32_t*)(g_atl + off0) = L;
        split2(oacc[nb][2] * inv1, oacc[nb][3] * inv1, H, L);
        size_t off1 = ((size_t)(b * SEQLEN + rowA + 8)) * DIM + d;
        *(uint32_t*)(g_ath + off1) = H;
        *(uint32_t*)(g_atl + off1) = L;
    }
}

// ---------------------------------------------------------------------------
// Launch
// ---------------------------------------------------------------------------
extern "C" void kernel_launch(void* const* d_in, const int* in_sizes, int n_in,
                              void* d_out, int out_size)
{
    const float* x  = (const float*)d_in[0];
    const float* wq = (const float*)d_in[1];
    const float* wk = (const float*)d_in[2];
    const float* wv = (const float*)d_in[3];
    const float* wo = (const float*)d_in[4];
    float* out = (float*)d_out;

    __half *pqh, *pql, *pkh, *pkl, *pvh, *pvl;
    __half *pxh, *pxl, *pwh, *pwl, *path, *patl;
    cudaGetSymbolAddress((void**)&pqh,  g_qh);
    cudaGetSymbolAddress((void**)&pql,  g_ql);
    cudaGetSymbolAddress((void**)&pkh,  g_kh);
    cudaGetSymbolAddress((void**)&pkl,  g_kl);
    cudaGetSymbolAddress((void**)&pvh,  g_vh);
    cudaGetSymbolAddress((void**)&pvl,  g_vl);
    cudaGetSymbolAddress((void**)&pxh,  g_xh);
    cudaGetSymbolAddress((void**)&pxl,  g_xl);
    cudaGetSymbolAddress((void**)&pwh,  g_wh);
    cudaGetSymbolAddress((void**)&pwl,  g_wl);
    cudaGetSymbolAddress((void**)&path, g_ath);
    cudaGetSymbolAddress((void**)&patl, g_atl);

    cudaFuncSetAttribute(gemm_fp16split_kernel,
                         cudaFuncAttributeMaxDynamicSharedMemorySize, GEMM_SMEM);
    cudaFuncSetAttribute(attn_hmma_kernel,
                         cudaFuncAttributeMaxDynamicSharedMemorySize, ATT_SMEM);

    // split x and weights to fp16 hi/lo
    {
        int n4x = MROWS * DIM / 4;
        split_fp16_kernel<<<n4x / 256, 256>>>((const float4*)x,
                                              (uint2*)pxh, (uint2*)pxl, n4x);
        int n4w = DIM * DIM / 4;
        const float* ws[4] = {wq, wk, wv, wo};
        for (int i = 0; i < 4; i++)
            split_fp16_kernel<<<n4w / 256, 256>>>((const float4*)ws[i],
                (uint2*)(pwh + (size_t)i * DIM * DIM),
                (uint2*)(pwl + (size_t)i * DIM * DIM), n4w);
    }

    dim3 ggrid(DIM / BN, MROWS / BM);   // (8, 64)

    gemm_fp16split_kernel<<<ggrid, 256, GEMM_SMEM>>>(
        pxh, pxl, pwh + 0 * (size_t)DIM * DIM, pwl + 0 * (size_t)DIM * DIM,
        pqh, pql, nullptr, 0);
    gemm_fp16split_kernel<<<ggrid, 256, GEMM_SMEM>>>(
        pxh, pxl, pwh + 1 * (size_t)DIM * DIM, pwl + 1 * (size_t)DIM * DIM,
        pkh, pkl, nullptr, 0);
    gemm_fp16split_kernel<<<ggrid, 256, GEMM_SMEM>>>(
        pxh, pxl, pwh + 2 * (size_t)DIM * DIM, pwl + 2 * (size_t)DIM * DIM,
        pvh, pvl, nullptr, 0);

    attn_hmma_kernel<<<dim3(SEQLEN / AQT, BHCOUNT), 256, ATT_SMEM>>>();

    gemm_fp16split_kernel<<<ggrid, 256, GEMM_SMEM>>>(
        path, patl, pwh + 3 * (size_t)DIM * DIM, pwl + 3 * (size_t)DIM * DIM,
        nullptr, nullptr, out, 1);
}